// round 14
// baseline (speedup 1.0000x reference)
#include <cuda_runtime.h>
#include <cstdint>

typedef unsigned long long u64;

#define BN      131072          // B*N
#define NPROP   16384
#define BIMG    8
#define NM      32768           // entries per image (incl. invalid)
#define CHUNK   256
#define DET     320
#define NMS_ITERS 640
#define BBOX_CLIP_F 4.135166556742356f

// static device scratch (no allocation allowed)
__device__ float4 g_box [BIMG * NM];   // clipped boxes by original m (valid only)
__device__ float4 g_nbox[BIMG * NM];   // offset boxes by original m (valid only)
__device__ u64    g_skey[BIMG * NM];   // keys (0 invalid); sorted desc in place

__device__ __forceinline__ u64 pack_key(float s, unsigned j)
{
    unsigned fb = __float_as_uint(s);
    fb = (fb & 0x80000000u) ? ~fb : (fb | 0x80000000u);   // sortable float
    return ((u64)fb << 32) | (u64)(0xFFFFFFFFu - j);
}

__device__ __forceinline__ float key_score(u64 k)
{
    unsigned fb = (unsigned)(k >> 32);
    unsigned orig = (fb & 0x80000000u) ? (fb ^ 0x80000000u) : ~fb;
    return __uint_as_float(orig);
}

// ---------------------------------------------------------------------------
// Prep: decode + softmax + clip + validity; key for EVERY m (0 if invalid)
// ---------------------------------------------------------------------------
__global__ void prep_kernel(const float* __restrict__ logits,
                            const float* __restrict__ breg,
                            const float* __restrict__ props)
{
    int g = blockIdx.x * blockDim.x + threadIdx.x;
    if (g >= BN) return;
    int b = g >> 14;
    int n = g & (NPROP - 1);

    float l0 = logits[g * 3 + 0];
    float l1 = logits[g * 3 + 1];
    float l2 = logits[g * 3 + 2];
    float mx = fmaxf(l0, fmaxf(l1, l2));
    float e0 = expf(l0 - mx), e1 = expf(l1 - mx), e2 = expf(l2 - mx);
    float sum = e0 + e1 + e2;
    float sc[2] = { e1 / sum, e2 / sum };

    float px1 = props[g * 4 + 0];
    float py1 = props[g * 4 + 1];
    float px2 = props[g * 4 + 2];
    float py2 = props[g * 4 + 3];
    float w  = px2 - px1;
    float h  = py2 - py1;
    float cx = px1 + 0.5f * w;
    float cy = py1 + 0.5f * h;

    const float fs = 1024.0f;

    #pragma unroll
    for (int c = 1; c <= 2; c++) {
        float r0 = breg[g * 12 + 4 * c + 0];
        float r1 = breg[g * 12 + 4 * c + 1];
        float r2 = breg[g * 12 + 4 * c + 2];
        float r3 = breg[g * 12 + 4 * c + 3];
        float dx = r0 / 10.0f;
        float dy = r1 / 10.0f;
        float dw = fminf(r2 / 5.0f, BBOX_CLIP_F);
        float dh = fminf(r3 / 5.0f, BBOX_CLIP_F);
        float pcx = dx * w + cx;
        float pcy = dy * h + cy;
        float pw = expf(dw) * w;
        float ph = expf(dh) * h;
        float x1 = pcx - 0.5f * pw;
        float y1 = pcy - 0.5f * ph;
        float x2 = pcx + 0.5f * pw;
        float y2 = pcy + 0.5f * ph;
        x1 = fminf(fmaxf(x1, 0.0f), fs);
        y1 = fminf(fmaxf(y1, 0.0f), fs);
        x2 = fminf(fmaxf(x2, 0.0f), fs);
        y2 = fminf(fmaxf(y2, 0.0f), fs);

        float s = sc[c - 1];
        bool valid = (s > 0.3f) && ((x2 - x1) >= 0.01f) && ((y2 - y1) >= 0.01f);
        float off = (float)c * (fs + 1.0f);   // 1025 / 2050 (exact)
        unsigned m = 2u * (unsigned)n + (unsigned)(c - 1);
        int o = b * NM + (int)m;
        g_skey[o] = valid ? pack_key(s, m) : 0ull;
        if (valid) {
            g_box [o] = make_float4(x1, y1, x2, y2);
            g_nbox[o] = make_float4(x1 + off, y1 + off, x2 + off, y2 + off);
        }
    }
}

// ---------------------------------------------------------------------------
// Bitonic sort (descending) per image, n = 32768. 4096-element smem tiles.
// ---------------------------------------------------------------------------
__global__ void __launch_bounds__(512, 1) sort_tileA()
{
    __shared__ u64 sk[4096];
    const int t = threadIdx.x;
    const int img  = blockIdx.x >> 3;
    const int tile = blockIdx.x & 7;
    const int gb = img * NM + tile * 4096;
    const int wb = tile * 4096;

    #pragma unroll
    for (int i = t; i < 4096; i += 512) sk[i] = g_skey[gb + i];
    __syncthreads();

    for (int k = 2; k <= 4096; k <<= 1) {
        for (int s = k >> 1; s > 0; s >>= 1) {
            for (int q = t; q < 2048; q += 512) {
                int i = (q << 1) - (q & (s - 1));
                int l = i + s;
                bool desc = (((wb + i) & k) == 0);
                u64 a = sk[i], c = sk[l];
                bool sw = desc ? (a < c) : (a > c);
                if (sw) { sk[i] = c; sk[l] = a; }
            }
            __syncthreads();
        }
    }
    #pragma unroll
    for (int i = t; i < 4096; i += 512) g_skey[gb + i] = sk[i];
}

__global__ void __launch_bounds__(512, 2) sort_gstep(int k, int s)
{
    int p = blockIdx.x * blockDim.x + threadIdx.x;   // 8 * 16384 pairs
    int img = p >> 14;
    int pl  = p & 16383;
    int i = (pl << 1) - (pl & (s - 1));
    u64* a = g_skey + img * NM;
    bool desc = ((i & k) == 0);
    u64 x = a[i], y = a[i + s];
    bool sw = desc ? (x < y) : (x > y);
    if (sw) { a[i] = y; a[i + s] = x; }
}

__global__ void __launch_bounds__(512, 1) sort_tileS(int k)
{
    __shared__ u64 sk[4096];
    const int t = threadIdx.x;
    const int img  = blockIdx.x >> 3;
    const int tile = blockIdx.x & 7;
    const int gb = img * NM + tile * 4096;
    const bool desc = (((tile * 4096) & k) == 0);    // uniform: k >= 8192

    #pragma unroll
    for (int i = t; i < 4096; i += 512) sk[i] = g_skey[gb + i];
    __syncthreads();

    for (int s = 2048; s > 0; s >>= 1) {
        for (int q = t; q < 2048; q += 512) {
            int i = (q << 1) - (q & (s - 1));
            int l = i + s;
            u64 a = sk[i], c = sk[l];
            bool sw = desc ? (a < c) : (a > c);
            if (sw) { sk[i] = c; sk[l] = a; }
        }
        __syncthreads();
    }
    #pragma unroll
    for (int i = t; i < 4096; i += 512) g_skey[gb + i] = sk[i];
}

// ---------------------------------------------------------------------------
// Walk: one CTA per image, all state in smem. Chunks of 256 sorted keys.
// Exact greedy: sorted order IS selection order; conflict-mask resolve.
// Dead-aware matrix + live-bit resolve.
// ---------------------------------------------------------------------------
__global__ void __launch_bounds__(1024, 1) walk_kernel(float* __restrict__ out)
{
    __shared__ u64      candKey[CHUNK];
    __shared__ float4   candBox[CHUNK];
    __shared__ float    candArea[CHUNK];
    __shared__ u64      killmask[CHUNK][4];
    __shared__ unsigned dead32[CHUNK / 32];
    __shared__ float4   selBox[NMS_ITERS];
    __shared__ float    selArea[NMS_ITERS];
    __shared__ unsigned recIdx[NMS_ITERS];
    __shared__ float    recScore[NMS_ITERS];
    __shared__ int      slots[NMS_ITERS];

    const int t = threadIdx.x;
    const int b = blockIdx.x;
    const int base = b * NM;

    int selCount = 0;

    for (int chunk = 0; chunk < NM / CHUNK; ++chunk) {
        // ---- phase A: load chunk, dead-from-invalid, clear masks ----------
        u64 myk = 0ull;
        if (t < CHUNK) {
            myk = g_skey[base + chunk * CHUNK + t];
            candKey[t] = myk;
            if (myk != 0ull) {
                unsigned m = 0xFFFFFFFFu - (unsigned)myk;
                float4 bb = g_nbox[base + (int)m];
                candBox[t]  = bb;
                candArea[t] = (bb.z - bb.x) * (bb.w - bb.y);
            }
            unsigned bal = __ballot_sync(0xffffffffu, myk == 0ull);
            if ((t & 31) == 0) dead32[t >> 5] = bal;
        }
        killmask[t >> 2][t & 3] = 0ull;
        __syncthreads();

        // ---- phase B: kill vs already-selected (atomicOr dead32) ----------
        {
            int j = t & (CHUNK - 1);
            u64 ck = candKey[j];
            if (ck != 0ull) {
                float4 cb = candBox[j];
                float ca = candArea[j];
                for (int s = t >> 8; s < selCount; s += 4) {
                    float4 sb = selBox[s];
                    float ltx = fmaxf(sb.x, cb.x);
                    float lty = fmaxf(sb.y, cb.y);
                    float rbx = fminf(sb.z, cb.z);
                    float rby = fminf(sb.w, cb.w);
                    float iw = fmaxf(rbx - ltx, 0.0f);
                    float ih = fmaxf(rby - lty, 0.0f);
                    float inter = iw * ih;
                    float iou = inter / (selArea[s] + ca - inter);
                    if (iou > 0.3f) {
                        atomicOr(&dead32[j >> 5], 1u << (j & 31));
                        break;
                    }
                }
            }
        }
        __syncthreads();

        // ---- phase C: intra-chunk conflict matrix (dead-aware) ------------
        {
            int jr  = t >> 2;
            int sub = t & 3;
            bool deadj = (dead32[jr >> 5] >> (jr & 31)) & 1u;
            int i0 = sub * 64;
            int i1 = i0 + 64; if (i1 > jr) i1 = jr;
            if (!deadj && i0 < i1) {
                u64 dWi = (u64)dead32[sub * 2] | ((u64)dead32[sub * 2 + 1] << 32);
                float4 bj = candBox[jr];
                float aj = candArea[jr];
                u64 m = 0ull;
                for (int i = i0; i < i1; i++) {
                    if ((dWi >> (i & 63)) & 1ull) continue;   // dead i never in acc
                    float4 bi = candBox[i];
                    float ai = candArea[i];
                    float ltx = fmaxf(bi.x, bj.x);
                    float lty = fmaxf(bi.y, bj.y);
                    float rbx = fminf(bi.z, bj.z);
                    float rby = fminf(bi.w, bj.w);
                    float iw = fmaxf(rbx - ltx, 0.0f);
                    float ih = fmaxf(rby - lty, 0.0f);
                    float inter = iw * ih;
                    float iou = inter / (ai + aj - inter);    // winner area first
                    if (iou > 0.3f) m |= 1ull << (i & 63);
                }
                killmask[jr][sub] = m;                        // unique writer
            }
        }
        __syncthreads();

        // ---- phase D: resolve over LIVE bits only (redundant, uniform) ----
        u64 acc0 = 0, acc1 = 0, acc2 = 0, acc3 = 0;
        int c0 = selCount;
        bool full = false;

#define RESOLVE_WORD(W, accW)                                                 \
        if (!full) {                                                          \
            u64 liveW = ~((u64)dead32[(W)*2] | ((u64)dead32[(W)*2+1] << 32)); \
            while (liveW) {                                                   \
                int jj = __ffsll((long long)liveW) - 1;                       \
                liveW &= liveW - 1;                                           \
                int j = ((W) << 6) | jj;                                      \
                u64 h = (killmask[j][0] & acc0) | (killmask[j][1] & acc1)     \
                      | (killmask[j][2] & acc2) | (killmask[j][3] & acc3);    \
                if (h == 0ull) {                                              \
                    if (c0 < NMS_ITERS) { accW |= (1ull << jj); c0++; }       \
                    else { full = true; break; }                              \
                }                                                             \
            }                                                                 \
        }
        RESOLVE_WORD(0, acc0)
        RESOLVE_WORD(1, acc1)
        RESOLVE_WORD(2, acc2)
        RESOLVE_WORD(3, acc3)
#undef RESOLVE_WORD

        // ---- append accepted (threads t<256; ranks from popcounts) --------
        if (t < CHUNK) {
            int jw = t >> 6, jj = t & 63;
            u64 aw = (jw == 0) ? acc0 : (jw == 1) ? acc1 : (jw == 2) ? acc2 : acc3;
            if ((aw >> jj) & 1ull) {
                int rank = selCount;
                if (jw > 0) rank += __popcll(acc0);
                if (jw > 1) rank += __popcll(acc1);
                if (jw > 2) rank += __popcll(acc2);
                rank += __popcll(aw & ((1ull << jj) - 1ull));
                selBox[rank]  = candBox[t];
                selArea[rank] = candArea[t];
                u64 kk = candKey[t];
                recIdx[rank]   = 0xFFFFFFFFu - (unsigned)kk;
                recScore[rank] = key_score(kk);
            }
        }
        selCount = c0;
        __syncthreads();

        // uniform exits: key stream exhausted (zeros at end) or cap reached
        if (candKey[CHUNK - 1] == 0ull) break;
        if (selCount >= NMS_ITERS) break;
    }

    // ------------------- epilogue ------------------------------------------
    const int nRec = selCount;
    float* oBoxes  = out;                         // [8][320][4]
    float* oScores = out + BIMG * DET * 4;        // [8][320]
    float* oLabels = out + BIMG * DET * 5;        // [8][320]

    for (int q = t; q < DET * 4; q += 1024) oBoxes[b * DET * 4 + q] = 0.0f;
    for (int q = t; q < DET;     q += 1024) { oScores[b * DET + q] = 0.0f; oLabels[b * DET + q] = 0.0f; }

    if (t == 0) {
        int c2 = 0;
        for (int r = 0; r < nRec; r++)
            if (recIdx[r] & 1u) c2++;             // label-2 entries (m odd)
        int p0 = 0, p1 = 0;
        for (int r = 0; r < nRec; r++) {
            int slot = (recIdx[r] & 1u) ? (p0++) : (c2 + p1++);
            slots[r] = slot;
        }
    }
    __syncthreads();

    for (int q = t; q < nRec; q += 1024) {
        int slot = slots[q];
        if (slot < DET) {
            unsigned i = recIdx[q];
            float4 bx = g_box[base + (int)i];
            float* dst = oBoxes + (b * DET + slot) * 4;
            dst[0] = bx.x; dst[1] = bx.y; dst[2] = bx.z; dst[3] = bx.w;
            oScores[b * DET + slot] = recScore[q];
            oLabels[b * DET + slot] = (float)((i & 1u) + 1u);
        }
    }
}

// ---------------------------------------------------------------------------
extern "C" void kernel_launch(void* const* d_in, const int* in_sizes, int n_in,
                              void* d_out, int out_size)
{
    (void)in_sizes; (void)n_in; (void)out_size;
    const float* logits = (const float*)d_in[0];
    const float* breg   = (const float*)d_in[1];
    const float* props  = (const float*)d_in[2];
    float* out = (float*)d_out;

    prep_kernel<<<BN / 256, 256>>>(logits, breg, props);

    sort_tileA<<<BIMG * 8, 512>>>();
    // stage k = 8192
    sort_gstep<<<256, 512>>>(8192, 4096);
    sort_tileS<<<BIMG * 8, 512>>>(8192);
    // stage k = 16384
    sort_gstep<<<256, 512>>>(16384, 8192);
    sort_gstep<<<256, 512>>>(16384, 4096);
    sort_tileS<<<BIMG * 8, 512>>>(16384);
    // stage k = 32768
    sort_gstep<<<256, 512>>>(32768, 16384);
    sort_gstep<<<256, 512>>>(32768, 8192);
    sort_gstep<<<256, 512>>>(32768, 4096);
    sort_tileS<<<BIMG * 8, 512>>>(32768);

    walk_kernel<<<BIMG, 1024>>>(out);
}

// round 15
// speedup vs baseline: 1.3714x; 1.3714x over previous
#include <cuda_runtime.h>
#include <cstdint>

typedef unsigned long long u64;

#define BN      131072          // B*N
#define NPROP   16384
#define BIMG    8
#define NM      32768           // entries per image (incl. invalid)
#define CHUNK   256
#define DET     320
#define NMS_ITERS 640
#define BBOX_CLIP_F 4.135166556742356f

// static device scratch (no allocation allowed)
__device__ float4 g_box [BIMG * NM];   // clipped boxes by original m (valid only)
__device__ float4 g_nbox[BIMG * NM];   // offset boxes by original m (valid only)
__device__ u64    g_skey[BIMG * NM];   // keys (0 invalid); sorted desc in place

__device__ __forceinline__ u64 pack_key(float s, unsigned j)
{
    unsigned fb = __float_as_uint(s);
    fb = (fb & 0x80000000u) ? ~fb : (fb | 0x80000000u);   // sortable float
    return ((u64)fb << 32) | (u64)(0xFFFFFFFFu - j);
}

__device__ __forceinline__ float key_score(u64 k)
{
    unsigned fb = (unsigned)(k >> 32);
    unsigned orig = (fb & 0x80000000u) ? (fb ^ 0x80000000u) : ~fb;
    return __uint_as_float(orig);
}

// ---------------------------------------------------------------------------
// Prep: decode + softmax + clip + validity; key for EVERY m (0 if invalid)
// ---------------------------------------------------------------------------
__global__ void prep_kernel(const float* __restrict__ logits,
                            const float* __restrict__ breg,
                            const float* __restrict__ props)
{
    int g = blockIdx.x * blockDim.x + threadIdx.x;
    if (g >= BN) return;
    int b = g >> 14;
    int n = g & (NPROP - 1);

    float l0 = logits[g * 3 + 0];
    float l1 = logits[g * 3 + 1];
    float l2 = logits[g * 3 + 2];
    float mx = fmaxf(l0, fmaxf(l1, l2));
    float e0 = expf(l0 - mx), e1 = expf(l1 - mx), e2 = expf(l2 - mx);
    float sum = e0 + e1 + e2;
    float sc[2] = { e1 / sum, e2 / sum };

    float px1 = props[g * 4 + 0];
    float py1 = props[g * 4 + 1];
    float px2 = props[g * 4 + 2];
    float py2 = props[g * 4 + 3];
    float w  = px2 - px1;
    float h  = py2 - py1;
    float cx = px1 + 0.5f * w;
    float cy = py1 + 0.5f * h;

    const float fs = 1024.0f;

    #pragma unroll
    for (int c = 1; c <= 2; c++) {
        float r0 = breg[g * 12 + 4 * c + 0];
        float r1 = breg[g * 12 + 4 * c + 1];
        float r2 = breg[g * 12 + 4 * c + 2];
        float r3 = breg[g * 12 + 4 * c + 3];
        float dx = r0 / 10.0f;
        float dy = r1 / 10.0f;
        float dw = fminf(r2 / 5.0f, BBOX_CLIP_F);
        float dh = fminf(r3 / 5.0f, BBOX_CLIP_F);
        float pcx = dx * w + cx;
        float pcy = dy * h + cy;
        float pw = expf(dw) * w;
        float ph = expf(dh) * h;
        float x1 = pcx - 0.5f * pw;
        float y1 = pcy - 0.5f * ph;
        float x2 = pcx + 0.5f * pw;
        float y2 = pcy + 0.5f * ph;
        x1 = fminf(fmaxf(x1, 0.0f), fs);
        y1 = fminf(fmaxf(y1, 0.0f), fs);
        x2 = fminf(fmaxf(x2, 0.0f), fs);
        y2 = fminf(fmaxf(y2, 0.0f), fs);

        float s = sc[c - 1];
        bool valid = (s > 0.3f) && ((x2 - x1) >= 0.01f) && ((y2 - y1) >= 0.01f);
        float off = (float)c * (fs + 1.0f);   // 1025 / 2050 (exact)
        unsigned m = 2u * (unsigned)n + (unsigned)(c - 1);
        int o = b * NM + (int)m;
        g_skey[o] = valid ? pack_key(s, m) : 0ull;
        if (valid) {
            g_box [o] = make_float4(x1, y1, x2, y2);
            g_nbox[o] = make_float4(x1 + off, y1 + off, x2 + off, y2 + off);
        }
    }
}

// ---------------------------------------------------------------------------
// Bitonic sort (descending) per image, n = 32768. 4096-element smem tiles.
// ---------------------------------------------------------------------------
__global__ void __launch_bounds__(512, 1) sort_tileA()
{
    __shared__ u64 sk[4096];
    const int t = threadIdx.x;
    const int img  = blockIdx.x >> 3;
    const int tile = blockIdx.x & 7;
    const int gb = img * NM + tile * 4096;
    const int wb = tile * 4096;

    #pragma unroll
    for (int i = t; i < 4096; i += 512) sk[i] = g_skey[gb + i];
    __syncthreads();

    for (int k = 2; k <= 4096; k <<= 1) {
        for (int s = k >> 1; s > 0; s >>= 1) {
            for (int q = t; q < 2048; q += 512) {
                int i = (q << 1) - (q & (s - 1));
                int l = i + s;
                bool desc = (((wb + i) & k) == 0);
                u64 a = sk[i], c = sk[l];
                bool sw = desc ? (a < c) : (a > c);
                if (sw) { sk[i] = c; sk[l] = a; }
            }
            __syncthreads();
        }
    }
    #pragma unroll
    for (int i = t; i < 4096; i += 512) g_skey[gb + i] = sk[i];
}

__global__ void __launch_bounds__(512, 2) sort_gstep(int k, int s)
{
    int p = blockIdx.x * blockDim.x + threadIdx.x;   // 8 * 16384 pairs
    int img = p >> 14;
    int pl  = p & 16383;
    int i = (pl << 1) - (pl & (s - 1));
    u64* a = g_skey + img * NM;
    bool desc = ((i & k) == 0);
    u64 x = a[i], y = a[i + s];
    bool sw = desc ? (x < y) : (x > y);
    if (sw) { a[i] = y; a[i + s] = x; }
}

__global__ void __launch_bounds__(512, 1) sort_tileS(int k)
{
    __shared__ u64 sk[4096];
    const int t = threadIdx.x;
    const int img  = blockIdx.x >> 3;
    const int tile = blockIdx.x & 7;
    const int gb = img * NM + tile * 4096;
    const bool desc = (((tile * 4096) & k) == 0);    // uniform: k >= 8192

    #pragma unroll
    for (int i = t; i < 4096; i += 512) sk[i] = g_skey[gb + i];
    __syncthreads();

    for (int s = 2048; s > 0; s >>= 1) {
        for (int q = t; q < 2048; q += 512) {
            int i = (q << 1) - (q & (s - 1));
            int l = i + s;
            u64 a = sk[i], c = sk[l];
            bool sw = desc ? (a < c) : (a > c);
            if (sw) { sk[i] = c; sk[l] = a; }
        }
        __syncthreads();
    }
    #pragma unroll
    for (int i = t; i < 4096; i += 512) g_skey[gb + i] = sk[i];
}

// ---------------------------------------------------------------------------
// Walk: one CTA per image, all state in smem. Chunks of 256 sorted keys.
// Exact greedy: sorted order IS selection order; conflict-mask resolve.
// inter>0 guard skips the MUFU divide on ~90% of pairs (exact: iou==0).
// ---------------------------------------------------------------------------
__global__ void __launch_bounds__(1024, 1) walk_kernel(float* __restrict__ out)
{
    __shared__ u64      candKey[CHUNK];
    __shared__ float4   candBox[CHUNK];
    __shared__ float    candArea[CHUNK];
    __shared__ u64      killmask[CHUNK][4];
    __shared__ unsigned dead32[CHUNK / 32];
    __shared__ float4   selBox[NMS_ITERS];
    __shared__ float    selArea[NMS_ITERS];
    __shared__ unsigned recIdx[NMS_ITERS];
    __shared__ float    recScore[NMS_ITERS];
    __shared__ int      slots[NMS_ITERS];

    const int t = threadIdx.x;
    const int b = blockIdx.x;
    const int base = b * NM;

    int selCount = 0;

    for (int chunk = 0; chunk < NM / CHUNK; ++chunk) {
        // ---- phase A: load chunk, dead-from-invalid, clear masks ----------
        u64 myk = 0ull;
        if (t < CHUNK) {
            myk = g_skey[base + chunk * CHUNK + t];
            candKey[t] = myk;
            if (myk != 0ull) {
                unsigned m = 0xFFFFFFFFu - (unsigned)myk;
                float4 bb = g_nbox[base + (int)m];
                candBox[t]  = bb;
                candArea[t] = (bb.z - bb.x) * (bb.w - bb.y);
            }
            unsigned bal = __ballot_sync(0xffffffffu, myk == 0ull);
            if ((t & 31) == 0) dead32[t >> 5] = bal;
        }
        killmask[t >> 2][t & 3] = 0ull;
        __syncthreads();

        // ---- phase B: kill vs already-selected (atomicOr dead32) ----------
        {
            int j = t & (CHUNK - 1);
            u64 ck = candKey[j];
            if (ck != 0ull) {
                float4 cb = candBox[j];
                float ca = candArea[j];
                for (int s = t >> 8; s < selCount; s += 4) {
                    float4 sb = selBox[s];
                    float ltx = fmaxf(sb.x, cb.x);
                    float lty = fmaxf(sb.y, cb.y);
                    float rbx = fminf(sb.z, cb.z);
                    float rby = fminf(sb.w, cb.w);
                    float iw = fmaxf(rbx - ltx, 0.0f);
                    float ih = fmaxf(rby - lty, 0.0f);
                    float inter = iw * ih;
                    if (inter > 0.0f) {               // exact: iou==0 otherwise
                        float iou = inter / (selArea[s] + ca - inter);
                        if (iou > 0.3f) {
                            atomicOr(&dead32[j >> 5], 1u << (j & 31));
                            break;
                        }
                    }
                }
            }
        }
        __syncthreads();

        // ---- phase C: intra-chunk conflict matrix (dead-aware) ------------
        {
            int jr  = t >> 2;
            int sub = t & 3;
            bool deadj = (dead32[jr >> 5] >> (jr & 31)) & 1u;
            int i0 = sub * 64;
            int i1 = i0 + 64; if (i1 > jr) i1 = jr;
            if (!deadj && i0 < i1) {
                u64 dWi = (u64)dead32[sub * 2] | ((u64)dead32[sub * 2 + 1] << 32);
                float4 bj = candBox[jr];
                float aj = candArea[jr];
                u64 m = 0ull;
                for (int i = i0; i < i1; i++) {
                    if ((dWi >> (i & 63)) & 1ull) continue;   // dead i never in acc
                    float4 bi = candBox[i];
                    float ai = candArea[i];
                    float ltx = fmaxf(bi.x, bj.x);
                    float lty = fmaxf(bi.y, bj.y);
                    float rbx = fminf(bi.z, bj.z);
                    float rby = fminf(bi.w, bj.w);
                    float iw = fmaxf(rbx - ltx, 0.0f);
                    float ih = fmaxf(rby - lty, 0.0f);
                    float inter = iw * ih;
                    if (inter > 0.0f) {               // exact: iou==0 otherwise
                        float iou = inter / (ai + aj - inter);   // winner area first
                        if (iou > 0.3f) m |= 1ull << (i & 63);
                    }
                }
                killmask[jr][sub] = m;                // unique writer
            }
        }
        __syncthreads();

        // ---- phase D: resolve over LIVE bits only (redundant, uniform) ----
        u64 acc0 = 0, acc1 = 0, acc2 = 0, acc3 = 0;
        int c0 = selCount;
        bool full = false;

#define RESOLVE_WORD(W, accW)                                                 \
        if (!full) {                                                          \
            u64 liveW = ~((u64)dead32[(W)*2] | ((u64)dead32[(W)*2+1] << 32)); \
            while (liveW) {                                                   \
                int jj = __ffsll((long long)liveW) - 1;                       \
                liveW &= liveW - 1;                                           \
                int j = ((W) << 6) | jj;                                      \
                u64 h = (killmask[j][0] & acc0) | (killmask[j][1] & acc1)     \
                      | (killmask[j][2] & acc2) | (killmask[j][3] & acc3);    \
                if (h == 0ull) {                                              \
                    if (c0 < NMS_ITERS) { accW |= (1ull << jj); c0++; }       \
                    else { full = true; break; }                              \
                }                                                             \
            }                                                                 \
        }
        RESOLVE_WORD(0, acc0)
        RESOLVE_WORD(1, acc1)
        RESOLVE_WORD(2, acc2)
        RESOLVE_WORD(3, acc3)
#undef RESOLVE_WORD

        // ---- append accepted (threads t<256; ranks from popcounts) --------
        if (t < CHUNK) {
            int jw = t >> 6, jj = t & 63;
            u64 aw = (jw == 0) ? acc0 : (jw == 1) ? acc1 : (jw == 2) ? acc2 : acc3;
            if ((aw >> jj) & 1ull) {
                int rank = selCount;
                if (jw > 0) rank += __popcll(acc0);
                if (jw > 1) rank += __popcll(acc1);
                if (jw > 2) rank += __popcll(acc2);
                rank += __popcll(aw & ((1ull << jj) - 1ull));
                selBox[rank]  = candBox[t];
                selArea[rank] = candArea[t];
                u64 kk = candKey[t];
                recIdx[rank]   = 0xFFFFFFFFu - (unsigned)kk;
                recScore[rank] = key_score(kk);
            }
        }
        selCount = c0;
        __syncthreads();

        // uniform exits: key stream exhausted (zeros at end) or cap reached
        if (candKey[CHUNK - 1] == 0ull) break;
        if (selCount >= NMS_ITERS) break;
    }

    // ------------------- epilogue ------------------------------------------
    const int nRec = selCount;
    float* oBoxes  = out;                         // [8][320][4]
    float* oScores = out + BIMG * DET * 4;        // [8][320]
    float* oLabels = out + BIMG * DET * 5;        // [8][320]

    for (int q = t; q < DET * 4; q += 1024) oBoxes[b * DET * 4 + q] = 0.0f;
    for (int q = t; q < DET;     q += 1024) { oScores[b * DET + q] = 0.0f; oLabels[b * DET + q] = 0.0f; }

    if (t == 0) {
        int c2 = 0;
        for (int r = 0; r < nRec; r++)
            if (recIdx[r] & 1u) c2++;             // label-2 entries (m odd)
        int p0 = 0, p1 = 0;
        for (int r = 0; r < nRec; r++) {
            int slot = (recIdx[r] & 1u) ? (p0++) : (c2 + p1++);
            slots[r] = slot;
        }
    }
    __syncthreads();

    for (int q = t; q < nRec; q += 1024) {
        int slot = slots[q];
        if (slot < DET) {
            unsigned i = recIdx[q];
            float4 bx = g_box[base + (int)i];
            float* dst = oBoxes + (b * DET + slot) * 4;
            dst[0] = bx.x; dst[1] = bx.y; dst[2] = bx.z; dst[3] = bx.w;
            oScores[b * DET + slot] = recScore[q];
            oLabels[b * DET + slot] = (float)((i & 1u) + 1u);
        }
    }
}

// ---------------------------------------------------------------------------
extern "C" void kernel_launch(void* const* d_in, const int* in_sizes, int n_in,
                              void* d_out, int out_size)
{
    (void)in_sizes; (void)n_in; (void)out_size;
    const float* logits = (const float*)d_in[0];
    const float* breg   = (const float*)d_in[1];
    const float* props  = (const float*)d_in[2];
    float* out = (float*)d_out;

    prep_kernel<<<BN / 256, 256>>>(logits, breg, props);

    sort_tileA<<<BIMG * 8, 512>>>();
    // stage k = 8192
    sort_gstep<<<256, 512>>>(8192, 4096);
    sort_tileS<<<BIMG * 8, 512>>>(8192);
    // stage k = 16384
    sort_gstep<<<256, 512>>>(16384, 8192);
    sort_gstep<<<256, 512>>>(16384, 4096);
    sort_tileS<<<BIMG * 8, 512>>>(16384);
    // stage k = 32768
    sort_gstep<<<256, 512>>>(32768, 16384);
    sort_gstep<<<256, 512>>>(32768, 8192);
    sort_gstep<<<256, 512>>>(32768, 4096);
    sort_tileS<<<BIMG * 8, 512>>>(32768);

    walk_kernel<<<BIMG, 1024>>>(out);
}

// round 17
// speedup vs baseline: 1.5209x; 1.1090x over previous
#include <cuda_runtime.h>
#include <cstdint>

typedef unsigned long long u64;

#define BN      131072          // B*N
#define NPROP   16384
#define BIMG    8
#define NM      32768           // entries per image (incl. invalid)
#define CHUNK   256
#define DET     320
#define NMS_ITERS 640
#define BBOX_CLIP_F 4.135166556742356f

// static device scratch (no allocation allowed)
__device__ float4 g_box [BIMG * NM];   // clipped boxes by original m (valid only)
__device__ float4 g_nbox[BIMG * NM];   // offset boxes by original m (valid only)
__device__ u64    g_skey[BIMG * NM];   // keys (0 invalid); sorted desc in place

__device__ __forceinline__ u64 pack_key(float s, unsigned j)
{
    unsigned fb = __float_as_uint(s);
    fb = (fb & 0x80000000u) ? ~fb : (fb | 0x80000000u);   // sortable float
    return ((u64)fb << 32) | (u64)(0xFFFFFFFFu - j);
}

__device__ __forceinline__ float key_score(u64 k)
{
    unsigned fb = (unsigned)(k >> 32);
    unsigned orig = (fb & 0x80000000u) ? (fb ^ 0x80000000u) : ~fb;
    return __uint_as_float(orig);
}

// ---------------------------------------------------------------------------
// Prep: decode + softmax + clip + validity; key for EVERY m (0 if invalid)
// ---------------------------------------------------------------------------
__global__ void prep_kernel(const float* __restrict__ logits,
                            const float* __restrict__ breg,
                            const float* __restrict__ props)
{
    int g = blockIdx.x * blockDim.x + threadIdx.x;
    if (g >= BN) return;
    int b = g >> 14;
    int n = g & (NPROP - 1);

    float l0 = logits[g * 3 + 0];
    float l1 = logits[g * 3 + 1];
    float l2 = logits[g * 3 + 2];
    float mx = fmaxf(l0, fmaxf(l1, l2));
    float e0 = expf(l0 - mx), e1 = expf(l1 - mx), e2 = expf(l2 - mx);
    float sum = e0 + e1 + e2;
    float sc[2] = { e1 / sum, e2 / sum };

    float px1 = props[g * 4 + 0];
    float py1 = props[g * 4 + 1];
    float px2 = props[g * 4 + 2];
    float py2 = props[g * 4 + 3];
    float w  = px2 - px1;
    float h  = py2 - py1;
    float cx = px1 + 0.5f * w;
    float cy = py1 + 0.5f * h;

    const float fs = 1024.0f;

    #pragma unroll
    for (int c = 1; c <= 2; c++) {
        float r0 = breg[g * 12 + 4 * c + 0];
        float r1 = breg[g * 12 + 4 * c + 1];
        float r2 = breg[g * 12 + 4 * c + 2];
        float r3 = breg[g * 12 + 4 * c + 3];
        float dx = r0 / 10.0f;
        float dy = r1 / 10.0f;
        float dw = fminf(r2 / 5.0f, BBOX_CLIP_F);
        float dh = fminf(r3 / 5.0f, BBOX_CLIP_F);
        float pcx = dx * w + cx;
        float pcy = dy * h + cy;
        float pw = expf(dw) * w;
        float ph = expf(dh) * h;
        float x1 = pcx - 0.5f * pw;
        float y1 = pcy - 0.5f * ph;
        float x2 = pcx + 0.5f * pw;
        float y2 = pcy + 0.5f * ph;
        x1 = fminf(fmaxf(x1, 0.0f), fs);
        y1 = fminf(fmaxf(y1, 0.0f), fs);
        x2 = fminf(fmaxf(x2, 0.0f), fs);
        y2 = fminf(fmaxf(y2, 0.0f), fs);

        float s = sc[c - 1];
        bool valid = (s > 0.3f) && ((x2 - x1) >= 0.01f) && ((y2 - y1) >= 0.01f);
        float off = (float)c * (fs + 1.0f);   // 1025 / 2050 (exact)
        unsigned m = 2u * (unsigned)n + (unsigned)(c - 1);
        int o = b * NM + (int)m;
        g_skey[o] = valid ? pack_key(s, m) : 0ull;
        if (valid) {
            g_box [o] = make_float4(x1, y1, x2, y2);
            g_nbox[o] = make_float4(x1 + off, y1 + off, x2 + off, y2 + off);
        }
    }
}

// ---------------------------------------------------------------------------
// Bitonic sort (descending) per image, n = 32768. 4096-element smem tiles.
// ---------------------------------------------------------------------------
__global__ void __launch_bounds__(512, 1) sort_tileA()
{
    __shared__ u64 sk[4096];
    const int t = threadIdx.x;
    const int img  = blockIdx.x >> 3;
    const int tile = blockIdx.x & 7;
    const int gb = img * NM + tile * 4096;
    const int wb = tile * 4096;

    #pragma unroll
    for (int i = t; i < 4096; i += 512) sk[i] = g_skey[gb + i];
    __syncthreads();

    for (int k = 2; k <= 4096; k <<= 1) {
        for (int s = k >> 1; s > 0; s >>= 1) {
            for (int q = t; q < 2048; q += 512) {
                int i = (q << 1) - (q & (s - 1));
                int l = i + s;
                bool desc = (((wb + i) & k) == 0);
                u64 a = sk[i], c = sk[l];
                bool sw = desc ? (a < c) : (a > c);
                if (sw) { sk[i] = c; sk[l] = a; }
            }
            __syncthreads();
        }
    }
    #pragma unroll
    for (int i = t; i < 4096; i += 512) g_skey[gb + i] = sk[i];
}

__global__ void __launch_bounds__(512, 2) sort_gstep(int k, int s)
{
    int p = blockIdx.x * blockDim.x + threadIdx.x;   // 8 * 16384 pairs
    int img = p >> 14;
    int pl  = p & 16383;
    int i = (pl << 1) - (pl & (s - 1));
    u64* a = g_skey + img * NM;
    bool desc = ((i & k) == 0);
    u64 x = a[i], y = a[i + s];
    bool sw = desc ? (x < y) : (x > y);
    if (sw) { a[i] = y; a[i + s] = x; }
}

__global__ void __launch_bounds__(512, 1) sort_tileS(int k)
{
    __shared__ u64 sk[4096];
    const int t = threadIdx.x;
    const int img  = blockIdx.x >> 3;
    const int tile = blockIdx.x & 7;
    const int gb = img * NM + tile * 4096;
    const bool desc = (((tile * 4096) & k) == 0);    // uniform: k >= 8192

    #pragma unroll
    for (int i = t; i < 4096; i += 512) sk[i] = g_skey[gb + i];
    __syncthreads();

    for (int s = 2048; s > 0; s >>= 1) {
        for (int q = t; q < 2048; q += 512) {
            int i = (q << 1) - (q & (s - 1));
            int l = i + s;
            u64 a = sk[i], c = sk[l];
            bool sw = desc ? (a < c) : (a > c);
            if (sw) { sk[i] = c; sk[l] = a; }
        }
        __syncthreads();
    }
    #pragma unroll
    for (int i = t; i < 4096; i += 512) g_skey[gb + i] = sk[i];
}

// ---------------------------------------------------------------------------
// Walk: one CTA per image. Chunks of 256 sorted keys; exact greedy.
// Per-class selected lists: cross-class IoU is exactly 0 (batched-nms
// offsets), so phase B tests only same-class selected boxes.
// ---------------------------------------------------------------------------
__global__ void __launch_bounds__(1024, 1) walk_kernel(float* __restrict__ out)
{
    __shared__ u64      candKey[CHUNK];
    __shared__ float4   candBox[CHUNK];
    __shared__ float    candArea[CHUNK];
    __shared__ u64      killmask[CHUNK][4];
    __shared__ unsigned dead32[CHUNK / 32];
    __shared__ unsigned odd32[CHUNK / 32];
    __shared__ float4   selBox1[NMS_ITERS];      // label 1 (m even)
    __shared__ float    selArea1[NMS_ITERS];
    __shared__ float4   selBox2[NMS_ITERS];      // label 2 (m odd)
    __shared__ float    selArea2[NMS_ITERS];
    __shared__ unsigned recIdx[NMS_ITERS];
    __shared__ float    recScore[NMS_ITERS];
    __shared__ short    slots[NMS_ITERS];

    const int t = threadIdx.x;
    const int b = blockIdx.x;
    const int base = b * NM;

    int selCount = 0;
    int n1 = 0, n2 = 0;                          // per-class counts (uniform)

    for (int chunk = 0; chunk < NM / CHUNK; ++chunk) {
        // ---- phase A: load chunk, dead/odd ballots, clear masks -----------
        u64 myk = 0ull;
        if (t < CHUNK) {
            myk = g_skey[base + chunk * CHUNK + t];
            candKey[t] = myk;
            bool oddc = false;
            if (myk != 0ull) {
                unsigned m = 0xFFFFFFFFu - (unsigned)myk;
                oddc = (m & 1u);
                float4 bb = g_nbox[base + (int)m];
                candBox[t]  = bb;
                candArea[t] = (bb.z - bb.x) * (bb.w - bb.y);
            }
            unsigned bdead = __ballot_sync(0xffffffffu, myk == 0ull);
            unsigned bodd  = __ballot_sync(0xffffffffu, oddc);
            if ((t & 31) == 0) { dead32[t >> 5] = bdead; odd32[t >> 5] = bodd; }
        }
        killmask[t >> 2][t & 3] = 0ull;
        __syncthreads();

        // ---- phase B: kill vs SAME-CLASS selected (atomicOr dead32) -------
        {
            int j = t & (CHUNK - 1);
            u64 ck = candKey[j];
            if (ck != 0ull) {
                unsigned m = 0xFFFFFFFFu - (unsigned)ck;
                bool oddc = (m & 1u);
                const float4* sbl = oddc ? selBox2  : selBox1;
                const float*  sal = oddc ? selArea2 : selArea1;
                int cntS          = oddc ? n2 : n1;
                float4 cb = candBox[j];
                float ca = candArea[j];
                for (int s = t >> 8; s < cntS; s += 4) {
                    float4 sb = sbl[s];
                    float ltx = fmaxf(sb.x, cb.x);
                    float lty = fmaxf(sb.y, cb.y);
                    float rbx = fminf(sb.z, cb.z);
                    float rby = fminf(sb.w, cb.w);
                    float iw = fmaxf(rbx - ltx, 0.0f);
                    float ih = fmaxf(rby - lty, 0.0f);
                    float inter = iw * ih;
                    if (inter > 0.0f) {               // exact: iou==0 otherwise
                        float iou = inter / (sal[s] + ca - inter);
                        if (iou > 0.3f) {
                            atomicOr(&dead32[j >> 5], 1u << (j & 31));
                            break;
                        }
                    }
                }
            }
        }
        __syncthreads();

        // ---- phase C: intra-chunk conflict matrix (dead-aware) ------------
        {
            int jr  = t >> 2;
            int sub = t & 3;
            bool deadj = (dead32[jr >> 5] >> (jr & 31)) & 1u;
            int i0 = sub * 64;
            int i1 = i0 + 64; if (i1 > jr) i1 = jr;
            if (!deadj && i0 < i1) {
                u64 dWi = (u64)dead32[sub * 2] | ((u64)dead32[sub * 2 + 1] << 32);
                float4 bj = candBox[jr];
                float aj = candArea[jr];
                u64 m = 0ull;
                for (int i = i0; i < i1; i++) {
                    if ((dWi >> (i & 63)) & 1ull) continue;   // dead i never in acc
                    float4 bi = candBox[i];
                    float ai = candArea[i];
                    float ltx = fmaxf(bi.x, bj.x);
                    float lty = fmaxf(bi.y, bj.y);
                    float rbx = fminf(bi.z, bj.z);
                    float rby = fminf(bi.w, bj.w);
                    float iw = fmaxf(rbx - ltx, 0.0f);
                    float ih = fmaxf(rby - lty, 0.0f);
                    float inter = iw * ih;
                    if (inter > 0.0f) {               // exact: iou==0 otherwise
                        float iou = inter / (ai + aj - inter);   // winner area first
                        if (iou > 0.3f) m |= 1ull << (i & 63);
                    }
                }
                killmask[jr][sub] = m;                // unique writer
            }
        }
        __syncthreads();

        // ---- phase D: resolve over LIVE bits only (redundant, uniform) ----
        u64 acc0 = 0, acc1 = 0, acc2 = 0, acc3 = 0;
        int c0 = selCount;
        bool full = false;

#define RESOLVE_WORD(W, accW)                                                 \
        if (!full) {                                                          \
            u64 liveW = ~((u64)dead32[(W)*2] | ((u64)dead32[(W)*2+1] << 32)); \
            while (liveW) {                                                   \
                int jj = __ffsll((long long)liveW) - 1;                       \
                liveW &= liveW - 1;                                           \
                int j = ((W) << 6) | jj;                                      \
                u64 h = (killmask[j][0] & acc0) | (killmask[j][1] & acc1)     \
                      | (killmask[j][2] & acc2) | (killmask[j][3] & acc3);    \
                if (h == 0ull) {                                              \
                    if (c0 < NMS_ITERS) { accW |= (1ull << jj); c0++; }       \
                    else { full = true; break; }                              \
                }                                                             \
            }                                                                 \
        }
        RESOLVE_WORD(0, acc0)
        RESOLVE_WORD(1, acc1)
        RESOLVE_WORD(2, acc2)
        RESOLVE_WORD(3, acc3)
#undef RESOLVE_WORD

        // ---- append accepted: combined rec + per-class sel lists ----------
        u64 odd0 = (u64)odd32[0] | ((u64)odd32[1] << 32);
        u64 odd1 = (u64)odd32[2] | ((u64)odd32[3] << 32);
        u64 odd2 = (u64)odd32[4] | ((u64)odd32[5] << 32);
        u64 odd3 = (u64)odd32[6] | ((u64)odd32[7] << 32);

        if (t < CHUNK) {
            int jw = t >> 6, jj = t & 63;
            u64 aw = (jw == 0) ? acc0 : (jw == 1) ? acc1 : (jw == 2) ? acc2 : acc3;
            if ((aw >> jj) & 1ull) {
                u64 kk = candKey[t];
                unsigned m = 0xFFFFFFFFu - (unsigned)kk;
                bool oddc = (m & 1u);
                // combined rank -> rec arrays (global greedy order)
                int rank = selCount;
                if (jw > 0) rank += __popcll(acc0);
                if (jw > 1) rank += __popcll(acc1);
                if (jw > 2) rank += __popcll(acc2);
                u64 below = (1ull << jj) - 1ull;
                rank += __popcll(aw & below);
                recIdx[rank]   = m;
                recScore[rank] = key_score(kk);
                // per-class rank -> class sel list
                u64 cm0 = oddc ? odd0 : ~odd0;
                u64 cm1 = oddc ? odd1 : ~odd1;
                u64 cm2 = oddc ? odd2 : ~odd2;
                u64 cm3 = oddc ? odd3 : ~odd3;
                u64 cmw = (jw == 0) ? cm0 : (jw == 1) ? cm1 : (jw == 2) ? cm2 : cm3;
                int crank = oddc ? n2 : n1;
                if (jw > 0) crank += __popcll(acc0 & cm0);
                if (jw > 1) crank += __popcll(acc1 & cm1);
                if (jw > 2) crank += __popcll(acc2 & cm2);
                crank += __popcll(aw & cmw & below);
                if (oddc) { selBox2[crank] = candBox[t]; selArea2[crank] = candArea[t]; }
                else      { selBox1[crank] = candBox[t]; selArea1[crank] = candArea[t]; }
            }
        }
        // uniform per-class count updates
        n2 += __popcll(acc0 & odd0) + __popcll(acc1 & odd1)
            + __popcll(acc2 & odd2) + __popcll(acc3 & odd3);
        n1 += (c0 - selCount)
            - (__popcll(acc0 & odd0) + __popcll(acc1 & odd1)
             + __popcll(acc2 & odd2) + __popcll(acc3 & odd3));
        selCount = c0;
        __syncthreads();

        // uniform exits: key stream exhausted (zeros at end) or cap reached
        if (candKey[CHUNK - 1] == 0ull) break;
        if (selCount >= NMS_ITERS) break;
    }

    // ------------------- epilogue ------------------------------------------
    const int nRec = selCount;
    float* oBoxes  = out;                         // [8][320][4]
    float* oScores = out + BIMG * DET * 4;        // [8][320]
    float* oLabels = out + BIMG * DET * 5;        // [8][320]

    for (int q = t; q < DET * 4; q += 1024) oBoxes[b * DET * 4 + q] = 0.0f;
    for (int q = t; q < DET;     q += 1024) { oScores[b * DET + q] = 0.0f; oLabels[b * DET + q] = 0.0f; }

    if (t == 0) {
        int c2 = 0;
        for (int r = 0; r < nRec; r++)
            if (recIdx[r] & 1u) c2++;             // label-2 entries (m odd)
        int p0 = 0, p1 = 0;
        for (int r = 0; r < nRec; r++) {
            int slot = (recIdx[r] & 1u) ? (p0++) : (c2 + p1++);
            slots[r] = (short)slot;
        }
    }
    __syncthreads();

    for (int q = t; q < nRec; q += 1024) {
        int slot = slots[q];
        if (slot < DET) {
            unsigned i = recIdx[q];
            float4 bx = g_box[base + (int)i];
            float* dst = oBoxes + (b * DET + slot) * 4;
            dst[0] = bx.x; dst[1] = bx.y; dst[2] = bx.z; dst[3] = bx.w;
            oScores[b * DET + slot] = recScore[q];
            oLabels[b * DET + slot] = (float)((i & 1u) + 1u);
        }
    }
}

// ---------------------------------------------------------------------------
extern "C" void kernel_launch(void* const* d_in, const int* in_sizes, int n_in,
                              void* d_out, int out_size)
{
    (void)in_sizes; (void)n_in; (void)out_size;
    const float* logits = (const float*)d_in[0];
    const float* breg   = (const float*)d_in[1];
    const float* props  = (const float*)d_in[2];
    float* out = (float*)d_out;

    prep_kernel<<<BN / 256, 256>>>(logits, breg, props);

    sort_tileA<<<BIMG * 8, 512>>>();
    // stage k = 8192
    sort_gstep<<<256, 512>>>(8192, 4096);
    sort_tileS<<<BIMG * 8, 512>>>(8192);
    // stage k = 16384
    sort_gstep<<<256, 512>>>(16384, 8192);
    sort_gstep<<<256, 512>>>(16384, 4096);
    sort_tileS<<<BIMG * 8, 512>>>(16384);
    // stage k = 32768
    sort_gstep<<<256, 512>>>(32768, 16384);
    sort_gstep<<<256, 512>>>(32768, 8192);
    sort_gstep<<<256, 512>>>(32768, 4096);
    sort_tileS<<<BIMG * 8, 512>>>(32768);

    walk_kernel<<<BIMG, 1024>>>(out);
}